// round 4
// baseline (speedup 1.0000x reference)
#include <cuda_runtime.h>

#define DD 16
#define HH 64
#define WW 64
#define NPOS (DD * HH * WW)   // 65536
#define COUT 64

// Scratch for projected q, k, v fields ([C][D*H*W], fp32). Static __device__
// globals are the sanctioned scratch mechanism (no allocations allowed).
__device__ float g_q[COUT * NPOS];
__device__ float g_k[COUT * NPOS];
__device__ float g_v[COUT * NPOS];

// ---------------------------------------------------------------------------
// Kernel 1: QKV projection.  out[o, p] = sum_c w[o][c] * x[c][p]
// Block tile: 64 outputs x 64 positions, 256 threads, 4x4 register blocking.
// blockIdx.y selects which of {q,k,v} (each weight matrix is exactly 64x64).
// ---------------------------------------------------------------------------
__global__ __launch_bounds__(256) void qkv_kernel(
    const float* __restrict__ x,
    const float* __restrict__ wq,
    const float* __restrict__ wk,
    const float* __restrict__ wv)
{
    __shared__ float xs[64][64];   // [c][p], p contiguous
    __shared__ float ws[64][65];   // [o][c], padded: bank = (o + c) % 32

    const int tid  = threadIdx.x;
    const int pos0 = blockIdx.x * 64;

    const float* wg;
    float* outp;
    if (blockIdx.y == 0)      { wg = wq; outp = g_q; }
    else if (blockIdx.y == 1) { wg = wk; outp = g_k; }
    else                      { wg = wv; outp = g_v; }

    // Coalesced loads into smem.
    #pragma unroll
    for (int i = 0; i < 16; i++) {
        int idx = tid + i * 256;           // 0..4095
        int o = idx >> 6, c = idx & 63;
        ws[o][c] = wg[idx];                // consecutive c -> conflict-free STS
    }
    #pragma unroll
    for (int i = 0; i < 16; i++) {
        int idx = tid + i * 256;
        int c = idx >> 6, p = idx & 63;
        xs[c][p] = x[c * NPOS + pos0 + p]; // 256B coalesced rows
    }
    __syncthreads();

    // Thread tile: outputs o = l, l+16, l+32, l+48 (l = tid&15)  -> distinct
    // smem banks on the padded ws reads; positions p = tp..tp+3 (float4).
    const int l  = tid & 15;
    const int tp = (tid >> 4) * 4;

    float acc[4][4];
    #pragma unroll
    for (int j = 0; j < 4; j++)
        #pragma unroll
        for (int i = 0; i < 4; i++) acc[j][i] = 0.f;

    #pragma unroll
    for (int c = 0; c < 64; c++) {
        float4 xv = *(const float4*)&xs[c][tp];
        float xr[4] = {xv.x, xv.y, xv.z, xv.w};
        float wr[4];
        #pragma unroll
        for (int j = 0; j < 4; j++) wr[j] = ws[l + j * 16][c];
        #pragma unroll
        for (int j = 0; j < 4; j++)
            #pragma unroll
            for (int i = 0; i < 4; i++)
                acc[j][i] = fmaf(wr[j], xr[i], acc[j][i]);
    }

    #pragma unroll
    for (int j = 0; j < 4; j++) {
        float4 r = make_float4(acc[j][0], acc[j][1], acc[j][2], acc[j][3]);
        *(float4*)&outp[(l + j * 16) * NPOS + pos0 + tp] = r;
    }
}

// ---------------------------------------------------------------------------
// Kernel 2: per-channel 3x3x3 windowed softmax attention.
// out[c,p] = sum_n softmax_n( q[c,p] * (k[c,p+n] + bias_c(n)) ) * v[c,p+n]
// Out-of-bounds neighbors: k contribution = 0 + bias (pad-before-bias), v = 0.
// Tile: 2x8x16 positions x 8 channels per block; halo 4x10x18 in smem.
// ---------------------------------------------------------------------------
#define TD 2
#define TH 8
#define TW 16
#define HD (TD + 2)
#define HHT (TH + 2)
#define HW (TW + 2)
#define HALO (HD * HHT * HW)     // 720

__global__ __launch_bounds__(256) void attn_kernel(
    const float* __restrict__ rel_d,
    const float* __restrict__ rel_h,
    const float* __restrict__ rel_w,
    float* __restrict__ out)
{
    __shared__ float ks[8][HD][HHT][HW];   // 23040 B
    __shared__ float vs[8][HD][HHT][HW];   // 23040 B
    __shared__ float bias_s[8][27];

    const int tid  = threadIdx.x;
    const int cblk = blockIdx.y;           // 8 channel blocks of 8
    const int bs   = blockIdx.x;
    const int bw = bs & 3;                 // W / TW = 4
    const int bh = (bs >> 2) & 7;         // H / TH = 8
    const int bd = bs >> 5;               // D / TD = 8
    const int d0 = bd * TD, h0 = bh * TH, w0 = bw * TW;

    // Per-channel relative-position bias (rel_d on channels 0..20 keyed by kd,
    // rel_h on 21..41 keyed by kh, rel_w on 42..63 keyed by kw).
    if (tid < 8 * 27) {
        int cl = tid / 27, n = tid % 27;
        int kd = n / 9, kh = (n / 3) % 3, kw = n % 3;
        int cg = cblk * 8 + cl;
        float b;
        if (cg < 21)      b = rel_d[cg * 3 + kd];
        else if (cg < 42) b = rel_h[(cg - 21) * 3 + kh];
        else              b = rel_w[(cg - 42) * 3 + kw];
        bias_s[cl][n] = b;
    }

    // Halo load (zero-fill outside the volume).
    for (int idx = tid; idx < 8 * HALO; idx += 256) {
        int cl = idx / HALO;
        int r  = idx % HALO;
        int dd = r / (HHT * HW);
        int r2 = r % (HHT * HW);
        int hh = r2 / HW;
        int ww = r2 % HW;
        int gd = d0 + dd - 1, gh = h0 + hh - 1, gw = w0 + ww - 1;
        float kv = 0.f, vv = 0.f;
        if ((unsigned)gd < DD && (unsigned)gh < HH && (unsigned)gw < WW) {
            int gi = (cblk * 8 + cl) * NPOS + (gd * HH + gh) * WW + gw;
            kv = g_k[gi];
            vv = g_v[gi];
        }
        ks[cl][dd][hh][ww] = kv;
        vs[cl][dd][hh][ww] = vv;
    }
    __syncthreads();

    const int tw = tid & 15;
    const int th = (tid >> 4) & 7;
    const int td = tid >> 7;
    const int gpos = ((d0 + td) * HH + (h0 + th)) * WW + (w0 + tw);

    for (int cl = 0; cl < 8; cl++) {
        int cg = cblk * 8 + cl;
        float qv = g_q[cg * NPOS + gpos];

        float s[27];
        float m = -1e30f;
        #pragma unroll
        for (int kd = 0; kd < 3; kd++)
            #pragma unroll
            for (int kh = 0; kh < 3; kh++)
                #pragma unroll
                for (int kw = 0; kw < 3; kw++) {
                    int n = kd * 9 + kh * 3 + kw;
                    float kk = ks[cl][td + kd][th + kh][tw + kw] + bias_s[cl][n];
                    float sv = qv * kk;
                    s[n] = sv;
                    m = fmaxf(m, sv);
                }

        float se = 0.f, sev = 0.f;
        #pragma unroll
        for (int kd = 0; kd < 3; kd++)
            #pragma unroll
            for (int kh = 0; kh < 3; kh++)
                #pragma unroll
                for (int kw = 0; kw < 3; kw++) {
                    int n = kd * 9 + kh * 3 + kw;
                    float e = __expf(s[n] - m);
                    se  += e;
                    sev = fmaf(e, vs[cl][td + kd][th + kh][tw + kw], sev);
                }

        out[cg * NPOS + gpos] = __fdividef(sev, se);
    }
}

// ---------------------------------------------------------------------------
// Launch
// ---------------------------------------------------------------------------
extern "C" void kernel_launch(void* const* d_in, const int* in_sizes, int n_in,
                              void* d_out, int out_size)
{
    const float* x     = (const float*)d_in[0];
    const float* w_q   = (const float*)d_in[1];
    const float* w_k   = (const float*)d_in[2];
    const float* w_v   = (const float*)d_in[3];
    const float* rel_d = (const float*)d_in[4];
    const float* rel_h = (const float*)d_in[5];
    const float* rel_w = (const float*)d_in[6];
    float* out = (float*)d_out;

    dim3 g1(NPOS / 64, 3);
    qkv_kernel<<<g1, 256>>>(x, w_q, w_k, w_v);

    dim3 g2((DD / TD) * (HH / TH) * (WW / TW), 8);   // 256 x 8
    attn_kernel<<<g2, 256>>>(rel_d, rel_h, rel_w, out);
}

// round 8
// speedup vs baseline: 1.2794x; 1.2794x over previous
#include <cuda_runtime.h>

#define DD 16
#define HH 64
#define WW 64
#define NPOS (DD * HH * WW)   // 65536
#define COUT 64

// Scratch for projected q, k, v fields ([C][D*H*W], fp32).
__device__ float g_q[COUT * NPOS];
__device__ float g_k[COUT * NPOS];
__device__ float g_v[COUT * NPOS];

// ---------------------------------------------------------------------------
// helpers
// ---------------------------------------------------------------------------
__device__ __forceinline__ float ex2f(float x) {
    float y;
    asm("ex2.approx.f32 %0, %1;" : "=f"(y) : "f"(x));
    return y;
}

__device__ __forceinline__ unsigned long long ffma2(
    unsigned long long a, unsigned long long b, unsigned long long c)
{
    unsigned long long d;
    asm("fma.rn.f32x2 %0, %1, %2, %3;" : "=l"(d) : "l"(a), "l"(b), "l"(c));
    return d;
}

__device__ __forceinline__ unsigned long long pack2(float lo, float hi) {
    unsigned long long p;
    asm("mov.b64 %0, {%1, %2};" : "=l"(p) : "f"(lo), "f"(hi));
    return p;
}

// ---------------------------------------------------------------------------
// Kernel 1: QKV projection with packed f32x2 FFMA.
// out[o, p] = sum_c w[o][c] * x[c][p]
// Block tile: 64 outputs x 128 positions, 256 threads.
// Thread tile: 4 outputs x 8 positions (4 f32x2 pairs per output).
// blockIdx.y selects {q,k,v}.
// ---------------------------------------------------------------------------
__global__ __launch_bounds__(256) void qkv_kernel(
    const float* __restrict__ x,
    const float* __restrict__ wq,
    const float* __restrict__ wk,
    const float* __restrict__ wv)
{
    __shared__ __align__(16) float xs[64][128];   // 32 KB  [c][p]
    __shared__ float ws[64][65];                  // 16.6 KB [o][c], padded

    const int tid  = threadIdx.x;
    const int pos0 = blockIdx.x * 128;

    const float* wg;
    float* outp;
    if (blockIdx.y == 0)      { wg = wq; outp = g_q; }
    else if (blockIdx.y == 1) { wg = wk; outp = g_k; }
    else                      { wg = wv; outp = g_v; }

    // Weights: 4096 floats, 16 per thread (coalesced; pad kills STS conflicts).
    #pragma unroll
    for (int i = 0; i < 16; i++) {
        int idx = tid + i * 256;
        ws[idx >> 6][idx & 63] = wg[idx];
    }
    // x tile: 8192 floats = 2048 float4, 8 per thread.
    #pragma unroll
    for (int i = 0; i < 8; i++) {
        int idx = tid + i * 256;            // float4 index
        int c = idx >> 5, p4 = (idx & 31) << 2;
        *(float4*)&xs[c][p4] = *(const float4*)&x[c * NPOS + pos0 + p4];
    }
    __syncthreads();

    const int l  = tid & 15;        // output lane: o = l + j*16
    const int pp = (tid >> 4) * 8;  // 8 consecutive positions

    unsigned long long acc[4][4];
    #pragma unroll
    for (int j = 0; j < 4; j++)
        #pragma unroll
        for (int i = 0; i < 4; i++) acc[j][i] = 0ull;

    #pragma unroll 4
    for (int c = 0; c < 64; c++) {
        // 8 positions = 4 packed pairs, via two 16B shared loads (broadcast).
        ulonglong2 xa = *(const ulonglong2*)&xs[c][pp];
        ulonglong2 xb = *(const ulonglong2*)&xs[c][pp + 4];
        unsigned long long xp[4] = {xa.x, xa.y, xb.x, xb.y};
        #pragma unroll
        for (int j = 0; j < 4; j++) {
            float w = ws[l + j * 16][c];
            unsigned long long wp = pack2(w, w);
            #pragma unroll
            for (int i = 0; i < 4; i++)
                acc[j][i] = ffma2(wp, xp[i], acc[j][i]);
        }
    }

    #pragma unroll
    for (int j = 0; j < 4; j++) {
        float* op = &outp[(l + j * 16) * NPOS + pos0 + pp];
        ulonglong2 r0; r0.x = acc[j][0]; r0.y = acc[j][1];
        ulonglong2 r1; r1.x = acc[j][2]; r1.y = acc[j][3];
        *(ulonglong2*)op       = r0;
        *(ulonglong2*)(op + 4) = r1;
    }
}

// ---------------------------------------------------------------------------
// Kernel 2: per-channel 3x3x3 windowed softmax attention.
// out[c,p] = sum_n softmax_n( q[c,p] * (k[c,p+n] + bias_c(n)) ) * v[c,p+n]
// bias_c depends on only one axis of n (kd / kh / kw by channel group).
// Unnormalized exp (scores bounded << 88), ex2.approx with q pre-scaled
// by log2(e).
// Tile: 2(D) x 16(H) x 32(W) positions x 2 channels per block; each thread
// produces 4 consecutive W outputs, sharing LDS.128 k/v row loads.
// ---------------------------------------------------------------------------
#define TD 2
#define TH 16
#define TW 32
#define HD (TD + 2)      // 4
#define HHT (TH + 2)     // 18
#define HW 36            // (TW+2) padded to multiple of 4 for LDS.128
#define HALO (HD * HHT * HW)   // 2592
#define CPB 2

__constant__ float c_log2e = 1.4426950408889634f;

template<int AX>
__device__ __forceinline__ void attn_inner(
    const float* __restrict__ kp, const float* __restrict__ vp,
    const float t[4], const float tb[4][3], float se[4], float sev[4])
{
    #pragma unroll
    for (int kd = 0; kd < 3; kd++) {
        #pragma unroll
        for (int kh = 0; kh < 3; kh++) {
            const float* kr = kp + (kd * HHT + kh) * HW;
            const float* vr = vp + (kd * HHT + kh) * HW;
            float4 ka = *(const float4*)kr;
            float4 kb = *(const float4*)(kr + 4);
            float4 va = *(const float4*)vr;
            float4 vb = *(const float4*)(vr + 4);
            float k6[6] = {ka.x, ka.y, ka.z, ka.w, kb.x, kb.y};
            float v6[6] = {va.x, va.y, va.z, va.w, vb.x, vb.y};
            #pragma unroll
            for (int kw = 0; kw < 3; kw++) {
                const int sel = (AX == 0) ? kd : (AX == 1) ? kh : kw;
                #pragma unroll
                for (int i = 0; i < 4; i++) {
                    float s = fmaf(t[i], k6[i + kw], tb[i][sel]);
                    float e = ex2f(s);
                    se[i]  += e;
                    sev[i]  = fmaf(e, v6[i + kw], sev[i]);
                }
            }
        }
    }
}

__global__ __launch_bounds__(256) void attn_kernel(
    const float* __restrict__ rel_d,
    const float* __restrict__ rel_h,
    const float* __restrict__ rel_w,
    float* __restrict__ out)
{
    __shared__ __align__(16) float ks[CPB][HD][HHT][HW];   // 20736 B
    __shared__ __align__(16) float vs[CPB][HD][HHT][HW];   // 20736 B
    __shared__ float bias_v[CPB][3];
    __shared__ int   axis_s[CPB];

    const int tid  = threadIdx.x;
    const int cblk = blockIdx.y;            // 32 channel blocks of 2
    const int bs   = blockIdx.x;            // 64 position blocks
    const int bw = bs & 1;                  // W/TW = 2
    const int bh = (bs >> 1) & 3;           // H/TH = 4
    const int bd = bs >> 3;                 // D/TD = 8
    const int d0 = bd * TD, h0 = bh * TH, w0 = bw * TW;

    // Per-channel axis bias (3 values each).
    if (tid < CPB * 3) {
        int cl = tid / 3, a = tid % 3;
        int cg = cblk * CPB + cl;
        float b; int ax;
        if (cg < 21)      { b = rel_d[cg * 3 + a];        ax = 0; }
        else if (cg < 42) { b = rel_h[(cg - 21) * 3 + a]; ax = 1; }
        else              { b = rel_w[(cg - 42) * 3 + a]; ax = 2; }
        bias_v[cl][a] = b;
        if (a == 0) axis_s[cl] = ax;
    }

    // Halo load (zero outside volume). 2 channels * 2592 = 5184 sites.
    for (int idx = tid; idx < CPB * HALO; idx += 256) {
        int cl = (idx >= HALO) ? 1 : 0;
        int r  = idx - cl * HALO;
        int dd = r / (HHT * HW);
        int r2 = r - dd * (HHT * HW);
        int hh = r2 / HW;
        int ww = r2 - hh * HW;
        int gd = d0 + dd - 1, gh = h0 + hh - 1, gw = w0 + ww - 1;
        float kv = 0.f, vv = 0.f;
        if ((unsigned)gd < DD && (unsigned)gh < HH && (unsigned)gw < WW) {
            int gi = (cblk * CPB + cl) * NPOS + (gd * HH + gh) * WW + gw;
            kv = g_k[gi];
            vv = g_v[gi];
        }
        ks[cl][0][0][r] = kv;   // flat write within channel slab
        vs[cl][0][0][r] = vv;
    }
    __syncthreads();

    const int tw4 = (tid & 7) * 4;          // 4 consecutive W outputs
    const int th  = (tid >> 3) & 15;
    const int td  = tid >> 7;
    const int gpos = ((d0 + td) * HH + (h0 + th)) * WW + (w0 + tw4);

    #pragma unroll
    for (int cl = 0; cl < CPB; cl++) {
        const int cg = cblk * CPB + cl;
        float4 qv = *(const float4*)&g_q[cg * NPOS + gpos];
        float t[4] = {qv.x * c_log2e, qv.y * c_log2e,
                      qv.z * c_log2e, qv.w * c_log2e};
        float tb[4][3];
        #pragma unroll
        for (int i = 0; i < 4; i++)
            #pragma unroll
            for (int a = 0; a < 3; a++)
                tb[i][a] = t[i] * bias_v[cl][a];

        float se[4]  = {0.f, 0.f, 0.f, 0.f};
        float sev[4] = {0.f, 0.f, 0.f, 0.f};

        const float* kp = &ks[cl][td][th][tw4];
        const float* vp = &vs[cl][td][th][tw4];

        int ax = axis_s[cl];
        if (ax == 0)      attn_inner<0>(kp, vp, t, tb, se, sev);
        else if (ax == 1) attn_inner<1>(kp, vp, t, tb, se, sev);
        else              attn_inner<2>(kp, vp, t, tb, se, sev);

        float4 r;
        r.x = __fdividef(sev[0], se[0]);
        r.y = __fdividef(sev[1], se[1]);
        r.z = __fdividef(sev[2], se[2]);
        r.w = __fdividef(sev[3], se[3]);
        *(float4*)&out[cg * NPOS + gpos] = r;
    }
}

// ---------------------------------------------------------------------------
// Launch
// ---------------------------------------------------------------------------
extern "C" void kernel_launch(void* const* d_in, const int* in_sizes, int n_in,
                              void* d_out, int out_size)
{
    const float* x     = (const float*)d_in[0];
    const float* w_q   = (const float*)d_in[1];
    const float* w_k   = (const float*)d_in[2];
    const float* w_v   = (const float*)d_in[3];
    const float* rel_d = (const float*)d_in[4];
    const float* rel_h = (const float*)d_in[5];
    const float* rel_w = (const float*)d_in[6];
    float* out = (float*)d_out;

    dim3 g1(NPOS / 128, 3);
    qkv_kernel<<<g1, 256>>>(x, w_q, w_k, w_v);

    dim3 g2((DD / TD) * (HH / TH) * (WW / TW), COUT / CPB);   // 64 x 32
    attn_kernel<<<g2, 256>>>(rel_d, rel_h, rel_w, out);
}

// round 10
// speedup vs baseline: 1.3351x; 1.0436x over previous
#include <cuda_runtime.h>

#define DD 16
#define HH 64
#define WW 64
#define NPOS (DD * HH * WW)   // 65536
#define COUT 64

// Scratch for projected q, k, v fields ([C][D*H*W], fp32).
__device__ float g_q[COUT * NPOS];
__device__ float g_k[COUT * NPOS];
__device__ float g_v[COUT * NPOS];

// ---------------------------------------------------------------------------
// helpers
// ---------------------------------------------------------------------------
__device__ __forceinline__ float ex2f(float x) {
    float y;
    asm("ex2.approx.f32 %0, %1;" : "=f"(y) : "f"(x));
    return y;
}

__device__ __forceinline__ unsigned long long ffma2(
    unsigned long long a, unsigned long long b, unsigned long long c)
{
    unsigned long long d;
    asm("fma.rn.f32x2 %0, %1, %2, %3;" : "=l"(d) : "l"(a), "l"(b), "l"(c));
    return d;
}

__device__ __forceinline__ unsigned long long pack2(float lo, float hi) {
    unsigned long long p;
    asm("mov.b64 %0, {%1, %2};" : "=l"(p) : "f"(lo), "f"(hi));
    return p;
}

// ---------------------------------------------------------------------------
// Kernel 1: QKV projection with packed f32x2 FFMA.
// out[o, p] = sum_c w[o][c] * x[c][p]
// Block tile: 64 outputs x 128 positions, 256 threads.
// Thread tile: 4 outputs x 8 positions (4 f32x2 pairs per output).
// blockIdx.y selects {q,k,v}.
// ---------------------------------------------------------------------------
__global__ __launch_bounds__(256) void qkv_kernel(
    const float* __restrict__ x,
    const float* __restrict__ wq,
    const float* __restrict__ wk,
    const float* __restrict__ wv)
{
    __shared__ __align__(16) float xs[64][128];   // 32 KB  [c][p]
    __shared__ float ws[64][65];                  // 16.6 KB [o][c], padded

    const int tid  = threadIdx.x;
    const int pos0 = blockIdx.x * 128;

    const float* wg;
    float* outp;
    if (blockIdx.y == 0)      { wg = wq; outp = g_q; }
    else if (blockIdx.y == 1) { wg = wk; outp = g_k; }
    else                      { wg = wv; outp = g_v; }

    // Weights: 4096 floats, 16 per thread (coalesced; pad kills STS conflicts).
    #pragma unroll
    for (int i = 0; i < 16; i++) {
        int idx = tid + i * 256;
        ws[idx >> 6][idx & 63] = wg[idx];
    }
    // x tile: 8192 floats = 2048 float4, 8 per thread.
    #pragma unroll
    for (int i = 0; i < 8; i++) {
        int idx = tid + i * 256;            // float4 index
        int c = idx >> 5, p4 = (idx & 31) << 2;
        *(float4*)&xs[c][p4] = *(const float4*)&x[c * NPOS + pos0 + p4];
    }
    __syncthreads();

    const int l  = tid & 15;        // output lane: o = l + j*16
    const int pp = (tid >> 4) * 8;  // 8 consecutive positions

    unsigned long long acc[4][4];
    #pragma unroll
    for (int j = 0; j < 4; j++)
        #pragma unroll
        for (int i = 0; i < 4; i++) acc[j][i] = 0ull;

    #pragma unroll 4
    for (int c = 0; c < 64; c++) {
        // 8 positions = 4 packed pairs, via two 16B shared loads (broadcast).
        ulonglong2 xa = *(const ulonglong2*)&xs[c][pp];
        ulonglong2 xb = *(const ulonglong2*)&xs[c][pp + 4];
        unsigned long long xp[4] = {xa.x, xa.y, xb.x, xb.y};
        #pragma unroll
        for (int j = 0; j < 4; j++) {
            float w = ws[l + j * 16][c];
            unsigned long long wp = pack2(w, w);
            #pragma unroll
            for (int i = 0; i < 4; i++)
                acc[j][i] = ffma2(wp, xp[i], acc[j][i]);
        }
    }

    #pragma unroll
    for (int j = 0; j < 4; j++) {
        float* op = &outp[(l + j * 16) * NPOS + pos0 + pp];
        ulonglong2 r0; r0.x = acc[j][0]; r0.y = acc[j][1];
        ulonglong2 r1; r1.x = acc[j][2]; r1.y = acc[j][3];
        *(ulonglong2*)op       = r0;
        *(ulonglong2*)(op + 4) = r1;
    }
}

// ---------------------------------------------------------------------------
// Kernel 2: per-channel 3x3x3 windowed softmax attention.
// out[c,p] = sum_n softmax_n( q[c,p] * (k[c,p+n] + bias_c(n)) ) * v[c,p+n]
// bias_c depends on only one axis of n (kd / kh / kw by channel group).
// Unnormalized exp (scores bounded << 88), ex2.approx with q pre-scaled
// by log2(e).
// Tile: 2(D) x 16(H) x 32(W) positions x 2 channels per block; each thread
// produces 4 consecutive W outputs, sharing LDS.128 k/v row loads.
// ---------------------------------------------------------------------------
#define TD 2
#define TH 16
#define TW 32
#define HD (TD + 2)      // 4
#define HHT (TH + 2)     // 18
#define HW 36            // (TW+2) padded to multiple of 4 for LDS.128
#define HALO (HD * HHT * HW)   // 2592
#define CPB 2

__constant__ float c_log2e = 1.4426950408889634f;

template<int AX>
__device__ __forceinline__ void attn_inner(
    const float* __restrict__ kp, const float* __restrict__ vp,
    const float t[4], const float tb[4][3], float se[4], float sev[4])
{
    #pragma unroll
    for (int kd = 0; kd < 3; kd++) {
        #pragma unroll
        for (int kh = 0; kh < 3; kh++) {
            const float* kr = kp + (kd * HHT + kh) * HW;
            const float* vr = vp + (kd * HHT + kh) * HW;
            float4 ka = *(const float4*)kr;
            float4 kb = *(const float4*)(kr + 4);
            float4 va = *(const float4*)vr;
            float4 vb = *(const float4*)(vr + 4);
            float k6[6] = {ka.x, ka.y, ka.z, ka.w, kb.x, kb.y};
            float v6[6] = {va.x, va.y, va.z, va.w, vb.x, vb.y};
            #pragma unroll
            for (int kw = 0; kw < 3; kw++) {
                const int sel = (AX == 0) ? kd : (AX == 1) ? kh : kw;
                #pragma unroll
                for (int i = 0; i < 4; i++) {
                    float s = fmaf(t[i], k6[i + kw], tb[i][sel]);
                    float e = ex2f(s);
                    se[i]  += e;
                    sev[i]  = fmaf(e, v6[i + kw], sev[i]);
                }
            }
        }
    }
}

__global__ __launch_bounds__(256) void attn_kernel(
    const float* __restrict__ rel_d,
    const float* __restrict__ rel_h,
    const float* __restrict__ rel_w,
    float* __restrict__ out)
{
    __shared__ __align__(16) float ks[CPB][HD][HHT][HW];   // 20736 B
    __shared__ __align__(16) float vs[CPB][HD][HHT][HW];   // 20736 B
    __shared__ float bias_v[CPB][3];
    __shared__ int   axis_s[CPB];

    const int tid  = threadIdx.x;
    const int cblk = blockIdx.y;            // 32 channel blocks of 2
    const int bs   = blockIdx.x;            // 64 position blocks
    const int bw = bs & 1;                  // W/TW = 2
    const int bh = (bs >> 1) & 3;           // H/TH = 4
    const int bd = bs >> 3;                 // D/TD = 8
    const int d0 = bd * TD, h0 = bh * TH, w0 = bw * TW;

    // Per-channel axis bias (3 values each).
    if (tid < CPB * 3) {
        int cl = tid / 3, a = tid % 3;
        int cg = cblk * CPB + cl;
        float b; int ax;
        if (cg < 21)      { b = rel_d[cg * 3 + a];        ax = 0; }
        else if (cg < 42) { b = rel_h[(cg - 21) * 3 + a]; ax = 1; }
        else              { b = rel_w[(cg - 42) * 3 + a]; ax = 2; }
        bias_v[cl][a] = b;
        if (a == 0) axis_s[cl] = ax;
    }

    // Halo load (zero outside volume). 2 channels * 2592 = 5184 sites.
    for (int idx = tid; idx < CPB * HALO; idx += 256) {
        int cl = (idx >= HALO) ? 1 : 0;
        int r  = idx - cl * HALO;
        int dd = r / (HHT * HW);
        int r2 = r - dd * (HHT * HW);
        int hh = r2 / HW;
        int ww = r2 - hh * HW;
        int gd = d0 + dd - 1, gh = h0 + hh - 1, gw = w0 + ww - 1;
        float kv = 0.f, vv = 0.f;
        if ((unsigned)gd < DD && (unsigned)gh < HH && (unsigned)gw < WW) {
            int gi = (cblk * CPB + cl) * NPOS + (gd * HH + gh) * WW + gw;
            kv = g_k[gi];
            vv = g_v[gi];
        }
        ks[cl][0][0][r] = kv;   // flat write within channel slab
        vs[cl][0][0][r] = vv;
    }
    __syncthreads();

    const int tw4 = (tid & 7) * 4;          // 4 consecutive W outputs
    const int th  = (tid >> 3) & 15;
    const int td  = tid >> 7;
    const int gpos = ((d0 + td) * HH + (h0 + th)) * WW + (w0 + tw4);

    #pragma unroll
    for (int cl = 0; cl < CPB; cl++) {
        const int cg = cblk * CPB + cl;
        float4 qv = *(const float4*)&g_q[cg * NPOS + gpos];
        float t[4] = {qv.x * c_log2e, qv.y * c_log2e,
                      qv.z * c_log2e, qv.w * c_log2e};
        float tb[4][3];
        #pragma unroll
        for (int i = 0; i < 4; i++)
            #pragma unroll
            for (int a = 0; a < 3; a++)
                tb[i][a] = t[i] * bias_v[cl][a];

        float se[4]  = {0.f, 0.f, 0.f, 0.f};
        float sev[4] = {0.f, 0.f, 0.f, 0.f};

        const float* kp = &ks[cl][td][th][tw4];
        const float* vp = &vs[cl][td][th][tw4];

        int ax = axis_s[cl];
        if (ax == 0)      attn_inner<0>(kp, vp, t, tb, se, sev);
        else if (ax == 1) attn_inner<1>(kp, vp, t, tb, se, sev);
        else              attn_inner<2>(kp, vp, t, tb, se, sev);

        float4 r;
        r.x = __fdividef(sev[0], se[0]);
        r.y = __fdividef(sev[1], se[1]);
        r.z = __fdividef(sev[2], se[2]);
        r.w = __fdividef(sev[3], se[3]);
        *(float4*)&out[cg * NPOS + gpos] = r;
    }
}

// ---------------------------------------------------------------------------
// Launch
// ---------------------------------------------------------------------------
extern "C" void kernel_launch(void* const* d_in, const int* in_sizes, int n_in,
                              void* d_out, int out_size)
{
    const float* x     = (const float*)d_in[0];
    const float* w_q   = (const float*)d_in[1];
    const float* w_k   = (const float*)d_in[2];
    const float* w_v   = (const float*)d_in[3];
    const float* rel_d = (const float*)d_in[4];
    const float* rel_h = (const float*)d_in[5];
    const float* rel_w = (const float*)d_in[6];
    float* out = (float*)d_out;

    dim3 g1(NPOS / 128, 3);
    qkv_kernel<<<g1, 256>>>(x, w_q, w_k, w_v);

    dim3 g2((DD / TD) * (HH / TH) * (WW / TW), COUT / CPB);   // 64 x 32
    attn_kernel<<<g2, 256>>>(rel_d, rel_h, rel_w, out);
}

// round 12
// speedup vs baseline: 1.7818x; 1.3345x over previous
#include <cuda_runtime.h>
#include <cuda_bf16.h>
#include <cstdint>

#define DD 16
#define HH 64
#define WW 64
#define NPOS (DD * HH * WW)   // 65536
#define COUT 64

__device__ float g_q[COUT * NPOS];
__device__ float g_k[COUT * NPOS];
__device__ float g_v[COUT * NPOS];

// ---------------------------------------------------------------------------
// helpers
// ---------------------------------------------------------------------------
__device__ __forceinline__ float ex2f(float x) {
    float y;
    asm("ex2.approx.f32 %0, %1;" : "=f"(y) : "f"(x));
    return y;
}

__device__ __forceinline__ uint32_t smem_u32(const void* p) {
    uint32_t a;
    asm("{ .reg .u64 t; cvta.to.shared.u64 t, %1; cvt.u32.u64 %0, t; }"
        : "=r"(a) : "l"(p));
    return a;
}

#define LDSM4(r, a)                                                            \
    asm volatile("ldmatrix.sync.aligned.m8n8.x4.shared.b16 {%0,%1,%2,%3}, [%4];" \
                 : "=r"((r)[0]), "=r"((r)[1]), "=r"((r)[2]), "=r"((r)[3])      \
                 : "r"(a))

#define LDSM4T(r, a)                                                           \
    asm volatile("ldmatrix.sync.aligned.m8n8.x4.trans.shared.b16 {%0,%1,%2,%3}, [%4];" \
                 : "=r"((r)[0]), "=r"((r)[1]), "=r"((r)[2]), "=r"((r)[3])      \
                 : "r"(a))

#define MMA16816(d, a, b0, b1)                                                 \
    asm volatile(                                                              \
        "mma.sync.aligned.m16n8k16.row.col.f32.bf16.bf16.f32 "                 \
        "{%0,%1,%2,%3}, {%4,%5,%6,%7}, {%8,%9}, {%0,%1,%2,%3};"                \
        : "+f"((d)[0]), "+f"((d)[1]), "+f"((d)[2]), "+f"((d)[3])               \
        : "r"((a)[0]), "r"((a)[1]), "r"((a)[2]), "r"((a)[3]),                  \
          "r"(b0), "r"(b1))

__device__ __forceinline__ void cvt_hl(float4 f, uint2& hv, uint2& lv) {
    __nv_bfloat16 h0 = __float2bfloat16(f.x);
    __nv_bfloat16 h1 = __float2bfloat16(f.y);
    __nv_bfloat16 h2 = __float2bfloat16(f.z);
    __nv_bfloat16 h3 = __float2bfloat16(f.w);
    __nv_bfloat16 l0 = __float2bfloat16(f.x - __bfloat162float(h0));
    __nv_bfloat16 l1 = __float2bfloat16(f.y - __bfloat162float(h1));
    __nv_bfloat16 l2 = __float2bfloat16(f.z - __bfloat162float(h2));
    __nv_bfloat16 l3 = __float2bfloat16(f.w - __bfloat162float(h3));
    hv.x = (uint32_t)__bfloat16_as_ushort(h0) | ((uint32_t)__bfloat16_as_ushort(h1) << 16);
    hv.y = (uint32_t)__bfloat16_as_ushort(h2) | ((uint32_t)__bfloat16_as_ushort(h3) << 16);
    lv.x = (uint32_t)__bfloat16_as_ushort(l0) | ((uint32_t)__bfloat16_as_ushort(l1) << 16);
    lv.y = (uint32_t)__bfloat16_as_ushort(l2) | ((uint32_t)__bfloat16_as_ushort(l3) << 16);
}

// ---------------------------------------------------------------------------
// Kernel 1: QKV projection with warp-level HMMA (mma.m16n8k16, bf16 3-term
// split: D = wh*xh + wh*xl + wl*xh, fp32 accumulate).
//   A = W [o][c] row-major (native)  -> ldmatrix.x4
//   B = x [c][pos] k-major row-major (native) -> ldmatrix.x4.trans
// Block: 384 threads = 12 warps = 3 matrices x 4 M-tiles; 128 positions.
// Weight smem region is reused for the x tile after A-frags are in registers.
// ---------------------------------------------------------------------------
#define WPITCH 72    // bf16 elems per weight row (144 B, 16B-aligned, +4 banks)
#define XPITCH 136   // bf16 elems per x row (272 B, 16B-aligned, +4 banks)
#define WSM_BYTES (6 * 64 * WPITCH * 2)   // 55296
#define XSM_BYTES (2 * 64 * XPITCH * 2)   // 34816
#define QKV_SMEM  WSM_BYTES               // max of the two (regions overlap)

__global__ __launch_bounds__(384) void qkv_mma(
    const float* __restrict__ x,
    const float* __restrict__ wq,
    const float* __restrict__ wk,
    const float* __restrict__ wv)
{
    extern __shared__ __align__(16) char sm[];
    __nv_bfloat16* wsm = (__nv_bfloat16*)sm;   // [3 mats][2 splits][64][WPITCH]
    __nv_bfloat16* xsm = (__nv_bfloat16*)sm;   // [2 splits][64][XPITCH] (reuse)

    const int tid  = threadIdx.x;
    const int wid  = tid >> 5;
    const int lane = tid & 31;
    const int pos0 = blockIdx.x * 128;

    // --- Stage weights as bf16 hi/lo: 3 * 64 * 64 floats = 3072 float4 ---
    #pragma unroll
    for (int i = 0; i < 8; i++) {
        int idx = tid + i * 384;               // 0..3071
        int mat = idx >> 10, r = idx & 1023;
        int o = r >> 4, c4 = (r & 15) * 4;
        const float* wp = (mat == 0) ? wq : (mat == 1) ? wk : wv;
        float4 f = *(const float4*)(wp + o * 64 + c4);
        uint2 hv, lv;
        cvt_hl(f, hv, lv);
        *(uint2*)(wsm + ((mat * 2 + 0) * 64 + o) * WPITCH + c4) = hv;
        *(uint2*)(wsm + ((mat * 2 + 1) * 64 + o) * WPITCH + c4) = lv;
    }
    __syncthreads();

    // --- Load A fragments (held for the whole block) ---
    const int mat = wid >> 2;                  // 0=q 1=k 2=v
    const int o0  = (wid & 3) * 16;
    const int arow = o0 + (lane & 15);
    const int acol = 8 * (lane >> 4);
    uint32_t ah[4][4], al[4][4];
    {
        uint32_t bh_ = smem_u32(wsm) + (uint32_t)(((mat * 2 + 0) * 64 + arow) * WPITCH) * 2;
        uint32_t bl_ = smem_u32(wsm) + (uint32_t)(((mat * 2 + 1) * 64 + arow) * WPITCH) * 2;
        #pragma unroll
        for (int kt = 0; kt < 4; kt++) {
            LDSM4(ah[kt], bh_ + (kt * 16 + acol) * 2);
            LDSM4(al[kt], bl_ + (kt * 16 + acol) * 2);
        }
    }
    __syncthreads();   // everyone done reading wsm; region reused for x

    // --- Stage x tile [64 ch][128 pos] as bf16 hi/lo: 2048 float4 ---
    #pragma unroll
    for (int i = 0; i < 6; i++) {
        int idx = tid + i * 384;
        if (idx < 2048) {
            int ch = idx >> 5, p4 = (idx & 31) * 4;
            float4 f = *(const float4*)(x + ch * NPOS + pos0 + p4);
            uint2 hv, lv;
            cvt_hl(f, hv, lv);
            *(uint2*)(xsm + (ch) * XPITCH + p4)        = hv;
            *(uint2*)(xsm + (64 + ch) * XPITCH + p4)   = lv;
        }
    }
    __syncthreads();

    // --- Main: 16 n-tiles of 8 positions ---
    float* dst = (mat == 0) ? g_q : (mat == 1) ? g_k : g_v;
    const int g  = lane >> 2;
    const int tg = lane & 3;
    const uint32_t xh_b = smem_u32(xsm) + (uint32_t)(lane * XPITCH) * 2;
    const uint32_t xl_b = xh_b + (uint32_t)(64 * XPITCH) * 2;
    const uint32_t krow32 = (uint32_t)(32 * XPITCH) * 2;

    float* obase = dst + (o0 + g) * NPOS + pos0 + 2 * tg;

    for (int nt = 0; nt < 16; nt++) {
        const int n0 = nt * 8;
        uint32_t bh[8], bl[8];
        LDSM4T(bh + 0, xh_b + n0 * 2);
        LDSM4T(bh + 4, xh_b + krow32 + n0 * 2);
        LDSM4T(bl + 0, xl_b + n0 * 2);
        LDSM4T(bl + 4, xl_b + krow32 + n0 * 2);

        float d[4] = {0.f, 0.f, 0.f, 0.f};
        #pragma unroll
        for (int kt = 0; kt < 4; kt++) {
            MMA16816(d, ah[kt], bh[2 * kt], bh[2 * kt + 1]);
            MMA16816(d, ah[kt], bl[2 * kt], bl[2 * kt + 1]);
            MMA16816(d, al[kt], bh[2 * kt], bh[2 * kt + 1]);
        }
        *(float2*)(obase + n0)            = make_float2(d[0], d[1]);
        *(float2*)(obase + n0 + 8 * NPOS) = make_float2(d[2], d[3]);
    }
}

// ---------------------------------------------------------------------------
// Kernel 2: per-channel 3x3x3 windowed softmax attention.
// Tile: 2(D) x 16(H) x 64(full W), 1 channel per block, 8 W-outputs/thread.
// Halo rows stored shifted by +2 (wwi = gw + 2); W edges statically zero.
// Lane mapping puts th in lanes 0-7 -> conflict-free LDS.128 phases.
// ---------------------------------------------------------------------------
#define AHW 68
__constant__ float c_log2e = 1.4426950408889634f;

template<int AX>
__device__ __forceinline__ void attn_core(
    const float (*ks)[18][AHW], const float (*vs)[18][AHW],
    int td, int th, int tw8,
    const float t[8], const float tb[8][3], float se[8], float sev[8])
{
    #pragma unroll
    for (int kd = 0; kd < 3; kd++)
        #pragma unroll
        for (int kh = 0; kh < 3; kh++) {
            const float* kr = &ks[td + kd][th + kh][tw8];
            const float* vr = &vs[td + kd][th + kh][tw8];
            float4 a0 = *(const float4*)kr;
            float4 a1 = *(const float4*)(kr + 4);
            float4 a2 = *(const float4*)(kr + 8);
            float4 b0 = *(const float4*)vr;
            float4 b1 = *(const float4*)(vr + 4);
            float4 b2 = *(const float4*)(vr + 8);
            float kk[12] = {a0.x, a0.y, a0.z, a0.w, a1.x, a1.y, a1.z, a1.w,
                            a2.x, a2.y, a2.z, a2.w};
            float vv[12] = {b0.x, b0.y, b0.z, b0.w, b1.x, b1.y, b1.z, b1.w,
                            b2.x, b2.y, b2.z, b2.w};
            #pragma unroll
            for (int kw = 0; kw < 3; kw++) {
                const int sel = (AX == 0) ? kd : (AX == 1) ? kh : kw;
                #pragma unroll
                for (int i = 0; i < 8; i++) {
                    float s = fmaf(t[i], kk[i + kw + 1], tb[i][sel]);
                    float e = ex2f(s);
                    se[i] += e;
                    sev[i] = fmaf(e, vv[i + kw + 1], sev[i]);
                }
            }
        }
}

__global__ __launch_bounds__(256) void attn_kernel(
    const float* __restrict__ rel_d,
    const float* __restrict__ rel_h,
    const float* __restrict__ rel_w,
    float* __restrict__ out)
{
    __shared__ __align__(16) float ks[4][18][AHW];   // 19584 B
    __shared__ __align__(16) float vs[4][18][AHW];

    const int tid = threadIdx.x;
    const int cg  = blockIdx.y;
    const int bs  = blockIdx.x;           // 32: bd(8) x bh(4)
    const int bh = bs & 3, bd = bs >> 2;
    const int d0 = bd * 2, h0 = bh * 16;

    // Interior halo: 2 arrays x 72 rows x 16 float4.
    for (int s = tid; s < 2304; s += 256) {
        int arr = (s >= 1152);
        int r = s - arr * 1152;
        int row = r >> 4, f = r & 15;
        int dd = row / 18, hh = row - dd * 18;
        int gd = d0 + dd - 1, gh = h0 + hh - 1;
        float4 v = make_float4(0.f, 0.f, 0.f, 0.f);
        if ((unsigned)gd < DD && (unsigned)gh < HH) {
            const float* src = arr ? g_v : g_k;
            v = *(const float4*)&src[cg * NPOS + (gd * HH + gh) * WW + 4 * f];
        }
        float* dstp = arr ? &vs[dd][hh][2 + 4 * f] : &ks[dd][hh][2 + 4 * f];
        *(float2*)dstp       = make_float2(v.x, v.y);
        *(float2*)(dstp + 2) = make_float2(v.z, v.w);
    }
    // W edges (wwi 0,1,66,67): always zero.
    for (int s = tid; s < 288; s += 256) {
        int row = s >> 2, c = s & 3;
        int dd = row / 18, hh = row - dd * 18;
        int wwi = (c < 2) ? c : 64 + c;
        ks[dd][hh][wwi] = 0.f;
        vs[dd][hh][wwi] = 0.f;
    }
    __syncthreads();

    float b[3];
    int ax;
    if (cg < 21) {
        ax = 0; b[0] = rel_d[cg*3]; b[1] = rel_d[cg*3+1]; b[2] = rel_d[cg*3+2];
    } else if (cg < 42) {
        int c2 = cg - 21;
        ax = 1; b[0] = rel_h[c2*3]; b[1] = rel_h[c2*3+1]; b[2] = rel_h[c2*3+2];
    } else {
        int c2 = cg - 42;
        ax = 2; b[0] = rel_w[c2*3]; b[1] = rel_w[c2*3+1]; b[2] = rel_w[c2*3+2];
    }

    // lanes: b0-2 = th_lo (conflict-free LDS phase), b3-5 = tw, b6 = th_hi, b7 = td
    const int th  = (tid & 7) | (((tid >> 6) & 1) << 3);
    const int tw8 = ((tid >> 3) & 7) * 8;
    const int td  = tid >> 7;
    const int gpos = ((d0 + td) * HH + (h0 + th)) * WW + tw8;

    float4 qa = *(const float4*)&g_q[cg * NPOS + gpos];
    float4 qb = *(const float4*)&g_q[cg * NPOS + gpos + 4];
    float t[8] = {qa.x * c_log2e, qa.y * c_log2e, qa.z * c_log2e, qa.w * c_log2e,
                  qb.x * c_log2e, qb.y * c_log2e, qb.z * c_log2e, qb.w * c_log2e};
    float tb[8][3];
    #pragma unroll
    for (int i = 0; i < 8; i++)
        #pragma unroll
        for (int a = 0; a < 3; a++) tb[i][a] = t[i] * b[a];

    float se[8], sev[8];
    #pragma unroll
    for (int i = 0; i < 8; i++) { se[i] = 0.f; sev[i] = 0.f; }

    if (ax == 0)      attn_core<0>(ks, vs, td, th, tw8, t, tb, se, sev);
    else if (ax == 1) attn_core<1>(ks, vs, td, th, tw8, t, tb, se, sev);
    else              attn_core<2>(ks, vs, td, th, tw8, t, tb, se, sev);

    float4 r0, r1;
    r0.x = __fdividef(sev[0], se[0]); r0.y = __fdividef(sev[1], se[1]);
    r0.z = __fdividef(sev[2], se[2]); r0.w = __fdividef(sev[3], se[3]);
    r1.x = __fdividef(sev[4], se[4]); r1.y = __fdividef(sev[5], se[5]);
    r1.z = __fdividef(sev[6], se[6]); r1.w = __fdividef(sev[7], se[7]);
    *(float4*)&out[cg * NPOS + gpos]     = r0;
    *(float4*)&out[cg * NPOS + gpos + 4] = r1;
}

// ---------------------------------------------------------------------------
// Launch
// ---------------------------------------------------------------------------
extern "C" void kernel_launch(void* const* d_in, const int* in_sizes, int n_in,
                              void* d_out, int out_size)
{
    const float* x     = (const float*)d_in[0];
    const float* w_q   = (const float*)d_in[1];
    const float* w_k   = (const float*)d_in[2];
    const float* w_v   = (const float*)d_in[3];
    const float* rel_d = (const float*)d_in[4];
    const float* rel_h = (const float*)d_in[5];
    const float* rel_w = (const float*)d_in[6];
    float* out = (float*)d_out;

    static bool attr_set = false;
    if (!attr_set) {
        cudaFuncSetAttribute(qkv_mma, cudaFuncAttributeMaxDynamicSharedMemorySize,
                             QKV_SMEM);
        attr_set = true;
    }
    qkv_mma<<<NPOS / 128, 384, QKV_SMEM>>>(x, w_q, w_k, w_v);

    dim3 g2(32, COUT);
    attn_kernel<<<g2, 256>>>(rel_d, rel_h, rel_w, out);
}

// round 16
// speedup vs baseline: 2.1500x; 1.2067x over previous
#include <cuda_runtime.h>
#include <cuda_bf16.h>
#include <cstdint>

#define DD 16
#define HH 64
#define WW 64
#define NPOS (DD * HH * WW)   // 65536
#define COUT 64

__device__ float g_q[COUT * NPOS];
__device__ float g_k[COUT * NPOS];
__device__ float g_v[COUT * NPOS];
__device__ __nv_bfloat16 g_wpk[6 * 64 * 64];   // [mat*2+split][o][c]

// ---------------------------------------------------------------------------
// helpers
// ---------------------------------------------------------------------------
__device__ __forceinline__ float ex2f(float x) {
    float y;
    asm("ex2.approx.f32 %0, %1;" : "=f"(y) : "f"(x));
    return y;
}

__device__ __forceinline__ uint32_t smem_u32(const void* p) {
    uint32_t a;
    asm("{ .reg .u64 t; cvta.to.shared.u64 t, %1; cvt.u32.u64 %0, t; }"
        : "=r"(a) : "l"(p));
    return a;
}

#define LDSM4(r, a)                                                            \
    asm volatile("ldmatrix.sync.aligned.m8n8.x4.shared.b16 {%0,%1,%2,%3}, [%4];" \
                 : "=r"((r)[0]), "=r"((r)[1]), "=r"((r)[2]), "=r"((r)[3])      \
                 : "r"(a))

#define LDSM4T(r, a)                                                           \
    asm volatile("ldmatrix.sync.aligned.m8n8.x4.trans.shared.b16 {%0,%1,%2,%3}, [%4];" \
                 : "=r"((r)[0]), "=r"((r)[1]), "=r"((r)[2]), "=r"((r)[3])      \
                 : "r"(a))

#define MMA16816(d, a, b0, b1)                                                 \
    asm volatile(                                                              \
        "mma.sync.aligned.m16n8k16.row.col.f32.bf16.bf16.f32 "                 \
        "{%0,%1,%2,%3}, {%4,%5,%6,%7}, {%8,%9}, {%0,%1,%2,%3};"                \
        : "+f"((d)[0]), "+f"((d)[1]), "+f"((d)[2]), "+f"((d)[3])               \
        : "r"((a)[0]), "r"((a)[1]), "r"((a)[2]), "r"((a)[3]),                  \
          "r"(b0), "r"(b1))

__device__ __forceinline__ void cvt_hl(float4 f, uint2& hv, uint2& lv) {
    __nv_bfloat16 h0 = __float2bfloat16(f.x);
    __nv_bfloat16 h1 = __float2bfloat16(f.y);
    __nv_bfloat16 h2 = __float2bfloat16(f.z);
    __nv_bfloat16 h3 = __float2bfloat16(f.w);
    __nv_bfloat16 l0 = __float2bfloat16(f.x - __bfloat162float(h0));
    __nv_bfloat16 l1 = __float2bfloat16(f.y - __bfloat162float(h1));
    __nv_bfloat16 l2 = __float2bfloat16(f.z - __bfloat162float(h2));
    __nv_bfloat16 l3 = __float2bfloat16(f.w - __bfloat162float(h3));
    hv.x = (uint32_t)__bfloat16_as_ushort(h0) | ((uint32_t)__bfloat16_as_ushort(h1) << 16);
    hv.y = (uint32_t)__bfloat16_as_ushort(h2) | ((uint32_t)__bfloat16_as_ushort(h3) << 16);
    lv.x = (uint32_t)__bfloat16_as_ushort(l0) | ((uint32_t)__bfloat16_as_ushort(l1) << 16);
    lv.y = (uint32_t)__bfloat16_as_ushort(l2) | ((uint32_t)__bfloat16_as_ushort(l3) << 16);
}

// ---------------------------------------------------------------------------
// Kernel 0: one-shot weight prepack to bf16 hi/lo.
// ---------------------------------------------------------------------------
__global__ void w_convert(const float* __restrict__ wq,
                          const float* __restrict__ wk,
                          const float* __restrict__ wv)
{
    int idx = blockIdx.x * 256 + threadIdx.x;   // 0..12287
    if (idx >= 3 * 4096) return;
    int mat = idx >> 12, r = idx & 4095;
    const float* wp = (mat == 0) ? wq : (mat == 1) ? wk : wv;
    float f = wp[r];
    __nv_bfloat16 h = __float2bfloat16(f);
    __nv_bfloat16 l = __float2bfloat16(f - __bfloat162float(h));
    g_wpk[(mat * 2 + 0) * 4096 + r] = h;
    g_wpk[(mat * 2 + 1) * 4096 + r] = l;
}

// ---------------------------------------------------------------------------
// Kernel 1: QKV projection with warp-level HMMA (mma.m16n8k16, bf16 3-term
// split: D = wh*xh + wh*xl + wl*xh, fp32 accumulate).
//   A = W [o][c] row-major (native)  -> ldmatrix.x4
//   B = x [c][pos] k-major row-major (native) -> ldmatrix.x4.trans
// Block: 384 threads = 12 warps = 3 matrices x 4 M-tiles; 128 positions.
// x tile is prefetched into registers before the weight phase.
// ---------------------------------------------------------------------------
#define WPITCH 72    // bf16 elems per weight row
#define XPITCH 136   // bf16 elems per x row
#define WSM_BYTES (6 * 64 * WPITCH * 2)   // 55296
#define QKV_SMEM  WSM_BYTES

__global__ __launch_bounds__(384) void qkv_mma(
    const float* __restrict__ x)
{
    extern __shared__ __align__(16) char sm[];
    __nv_bfloat16* wsm = (__nv_bfloat16*)sm;   // [6*64][WPITCH]
    __nv_bfloat16* xsm = (__nv_bfloat16*)sm;   // [2*64][XPITCH] (reuse)

    const int tid  = threadIdx.x;
    const int wid  = tid >> 5;
    const int lane = tid & 31;
    const int pos0 = blockIdx.x * 128;

    // --- Prefetch x tile into registers (hide DRAM latency) ---
    float4 xf[6];
    #pragma unroll
    for (int i = 0; i < 6; i++) {
        int idx = tid + i * 384;
        if (idx < 2048) {
            int ch = idx >> 5, p4 = (idx & 31) * 4;
            xf[i] = *(const float4*)(x + ch * NPOS + pos0 + p4);
        }
    }

    // --- Stage prepacked weights: 3072 uint4 copies ---
    #pragma unroll
    for (int i = 0; i < 8; i++) {
        int idx = tid + i * 384;               // uint4 units
        int row = idx >> 3;                    // 0..383
        int c16 = (idx & 7) * 8;
        uint4 v = *(const uint4*)(g_wpk + row * 64 + c16);
        *(uint4*)(wsm + row * WPITCH + c16) = v;
    }
    __syncthreads();

    // --- Load A fragments (held for the whole block) ---
    const int mat = wid >> 2;                  // 0=q 1=k 2=v
    const int o0  = (wid & 3) * 16;
    const int arow = o0 + (lane & 15);
    const int acol = 8 * (lane >> 4);
    uint32_t ah[4][4], al[4][4];
    {
        uint32_t bh_ = smem_u32(wsm) + (uint32_t)(((mat * 2 + 0) * 64 + arow) * WPITCH) * 2;
        uint32_t bl_ = smem_u32(wsm) + (uint32_t)(((mat * 2 + 1) * 64 + arow) * WPITCH) * 2;
        #pragma unroll
        for (int kt = 0; kt < 4; kt++) {
            LDSM4(ah[kt], bh_ + (kt * 16 + acol) * 2);
            LDSM4(al[kt], bl_ + (kt * 16 + acol) * 2);
        }
    }
    __syncthreads();   // wsm reads done; region reused for x

    // --- Convert + store prefetched x tile ---
    #pragma unroll
    for (int i = 0; i < 6; i++) {
        int idx = tid + i * 384;
        if (idx < 2048) {
            int ch = idx >> 5, p4 = (idx & 31) * 4;
            uint2 hv, lv;
            cvt_hl(xf[i], hv, lv);
            *(uint2*)(xsm + ch * XPITCH + p4)        = hv;
            *(uint2*)(xsm + (64 + ch) * XPITCH + p4) = lv;
        }
    }
    __syncthreads();

    // --- Main: 16 n-tiles of 8 positions ---
    float* dst = (mat == 0) ? g_q : (mat == 1) ? g_k : g_v;
    const int g  = lane >> 2;
    const int tg = lane & 3;
    const uint32_t xh_b = smem_u32(xsm) + (uint32_t)(lane * XPITCH) * 2;
    const uint32_t xl_b = xh_b + (uint32_t)(64 * XPITCH) * 2;
    const uint32_t krow32 = (uint32_t)(32 * XPITCH) * 2;

    float* obase = dst + (o0 + g) * NPOS + pos0 + 2 * tg;

    for (int nt = 0; nt < 16; nt++) {
        const int n0 = nt * 8;
        uint32_t bh[8], bl[8];
        LDSM4T(bh + 0, xh_b + n0 * 2);
        LDSM4T(bh + 4, xh_b + krow32 + n0 * 2);
        LDSM4T(bl + 0, xl_b + n0 * 2);
        LDSM4T(bl + 4, xl_b + krow32 + n0 * 2);

        float d[4] = {0.f, 0.f, 0.f, 0.f};
        #pragma unroll
        for (int kt = 0; kt < 4; kt++) {
            MMA16816(d, ah[kt], bh[2 * kt], bh[2 * kt + 1]);
            MMA16816(d, ah[kt], bl[2 * kt], bl[2 * kt + 1]);
            MMA16816(d, al[kt], bh[2 * kt], bh[2 * kt + 1]);
        }
        *(float2*)(obase + n0)            = make_float2(d[0], d[1]);
        *(float2*)(obase + n0 + 8 * NPOS) = make_float2(d[2], d[3]);
    }
}

// ---------------------------------------------------------------------------
// Kernel 2: per-channel 3x3x3 windowed softmax attention.
// Tile: 2(D) x 8(H) x 64(full W), 1 channel per block, 4 W-outputs/thread.
// Halo stored +2-shifted in W; W edges statically zero. 256 threads, forced
// 4 CTAs/SM via launch_bounds for occupancy.
// ---------------------------------------------------------------------------
#define AHW 68
__constant__ float c_log2e = 1.4426950408889634f;

template<int AX>
__device__ __forceinline__ void attn_core(
    const float (*ks)[10][AHW], const float (*vs)[10][AHW],
    int td, int th, int tw4,
    const float t[4], const float tb[4][3], float se[4], float sev[4])
{
    #pragma unroll
    for (int kd = 0; kd < 3; kd++)
        #pragma unroll
        for (int kh = 0; kh < 3; kh++) {
            const float* kr = &ks[td + kd][th + kh][tw4];
            const float* vr = &vs[td + kd][th + kh][tw4];
            float4 a0 = *(const float4*)kr;
            float4 a1 = *(const float4*)(kr + 4);
            float4 b0 = *(const float4*)vr;
            float4 b1 = *(const float4*)(vr + 4);
            float kk[8] = {a0.x, a0.y, a0.z, a0.w, a1.x, a1.y, a1.z, a1.w};
            float vv[8] = {b0.x, b0.y, b0.z, b0.w, b1.x, b1.y, b1.z, b1.w};
            #pragma unroll
            for (int kw = 0; kw < 3; kw++) {
                const int sel = (AX == 0) ? kd : (AX == 1) ? kh : kw;
                #pragma unroll
                for (int i = 0; i < 4; i++) {
                    float s = fmaf(t[i], kk[i + kw + 1], tb[i][sel]);
                    float e = ex2f(s);
                    se[i] += e;
                    sev[i] = fmaf(e, vv[i + kw + 1], sev[i]);
                }
            }
        }
}

__global__ __launch_bounds__(256, 4) void attn_kernel(
    const float* __restrict__ rel_d,
    const float* __restrict__ rel_h,
    const float* __restrict__ rel_w,
    float* __restrict__ out)
{
    __shared__ __align__(16) float ks[4][10][AHW];   // 10880 B
    __shared__ __align__(16) float vs[4][10][AHW];

    const int tid = threadIdx.x;
    const int cg  = blockIdx.y;
    const int bs  = blockIdx.x;           // 64: bd(8) x bh(8)
    const int bh = bs & 7, bd = bs >> 3;
    const int d0 = bd * 2, h0 = bh * 8;

    // Interior halo: 2 arrays x 40 rows x 16 float4 = 1280.
    for (int s = tid; s < 1280; s += 256) {
        int arr = (s >= 640);
        int r = s - arr * 640;
        int row = r >> 4, f = r & 15;
        int dd = row / 10, hh = row - dd * 10;
        int gd = d0 + dd - 1, gh = h0 + hh - 1;
        float4 v = make_float4(0.f, 0.f, 0.f, 0.f);
        if ((unsigned)gd < DD && (unsigned)gh < HH) {
            const float* src = arr ? g_v : g_k;
            v = *(const float4*)&src[cg * NPOS + (gd * HH + gh) * WW + 4 * f];
        }
        float* dstp = arr ? &vs[dd][hh][2 + 4 * f] : &ks[dd][hh][2 + 4 * f];
        *(float2*)dstp       = make_float2(v.x, v.y);
        *(float2*)(dstp + 2) = make_float2(v.z, v.w);
    }
    // W edges (wwi 0,1,66,67): always zero. 40 rows x 2 arrays x 4 = 320.
    for (int s = tid; s < 320; s += 256) {
        int row = s >> 3;
        int rem = s & 7;
        int arr = rem >> 2, c = rem & 3;
        int dd = row / 10, hh = row - dd * 10;
        int wwi = (c < 2) ? c : 64 + c;
        if (arr) vs[dd][hh][wwi] = 0.f;
        else     ks[dd][hh][wwi] = 0.f;
    }
    __syncthreads();

    float b[3];
    int ax;
    if (cg < 21) {
        ax = 0; b[0] = rel_d[cg*3]; b[1] = rel_d[cg*3+1]; b[2] = rel_d[cg*3+2];
    } else if (cg < 42) {
        int c2 = cg - 21;
        ax = 1; b[0] = rel_h[c2*3]; b[1] = rel_h[c2*3+1]; b[2] = rel_h[c2*3+2];
    } else {
        int c2 = cg - 42;
        ax = 2; b[0] = rel_w[c2*3]; b[1] = rel_w[c2*3+1]; b[2] = rel_w[c2*3+2];
    }

    const int tw4 = (tid & 15) * 4;
    const int th  = (tid >> 4) & 7;
    const int td  = tid >> 7;
    const int gpos = ((d0 + td) * HH + (h0 + th)) * WW + tw4;

    float4 qa = *(const float4*)&g_q[cg * NPOS + gpos];
    float t[4] = {qa.x * c_log2e, qa.y * c_log2e, qa.z * c_log2e, qa.w * c_log2e};
    float tb[4][3];
    #pragma unroll
    for (int i = 0; i < 4; i++)
        #pragma unroll
        for (int a = 0; a < 3; a++) tb[i][a] = t[i] * b[a];

    float se[4], sev[4];
    #pragma unroll
    for (int i = 0; i < 4; i++) { se[i] = 0.f; sev[i] = 0.f; }

    if (ax == 0)      attn_core<0>(ks, vs, td, th, tw4, t, tb, se, sev);
    else if (ax == 1) attn_core<1>(ks, vs, td, th, tw4, t, tb, se, sev);
    else              attn_core<2>(ks, vs, td, th, tw4, t, tb, se, sev);

    float4 r;
    r.x = __fdividef(sev[0], se[0]);
    r.y = __fdividef(sev[1], se[1]);
    r.z = __fdividef(sev[2], se[2]);
    r.w = __fdividef(sev[3], se[3]);
    *(float4*)&out[cg * NPOS + gpos] = r;
}

// ---------------------------------------------------------------------------
// Launch
// ---------------------------------------------------------------------------
extern "C" void kernel_launch(void* const* d_in, const int* in_sizes, int n_in,
                              void* d_out, int out_size)
{
    const float* x     = (const float*)d_in[0];
    const float* w_q   = (const float*)d_in[1];
    const float* w_k   = (const float*)d_in[2];
    const float* w_v   = (const float*)d_in[3];
    const float* rel_d = (const float*)d_in[4];
    const float* rel_h = (const float*)d_in[5];
    const float* rel_w = (const float*)d_in[6];
    float* out = (float*)d_out;

    static bool attr_set = false;
    if (!attr_set) {
        cudaFuncSetAttribute(qkv_mma, cudaFuncAttributeMaxDynamicSharedMemorySize,
                             QKV_SMEM);
        attr_set = true;
    }

    w_convert<<<48, 256>>>(w_q, w_k, w_v);
    qkv_mma<<<NPOS / 128, 384, QKV_SMEM>>>(x);

    dim3 g2(64, COUT);
    attn_kernel<<<g2, 256>>>(rel_d, rel_h, rel_w, out);
}